// round 9
// baseline (speedup 1.0000x reference)
#include <cuda_runtime.h>
#include <math_constants.h>
#include <stdint.h>

// N=4096 mention-ranking loss, row-paired CTAs {b, 4095-b}, one streaming pass.
// Minimal-wavefront: mask + ana both via aligned LDG.256 (+L2::evict_last).
// ana misalignment (sh = abase&7, row-uniform) resolved by shfl_down window
// sharing. FIX vs R8: the corrective next-block load must fire whenever the
// NEIGHBOR lane does not hold group idx+1, i.e. lane==31 || base+lane+1 >= nv
// (clamped neighbors hold group nv-1, not idx+1).

#define NMENT 4096
#define BLOCK 128

struct F8 { float f[8]; };

__device__ __forceinline__ F8 ldg_el8(const float* p)
{
    uint32_t a0,a1,a2,a3,a4,a5,a6,a7;
    asm("ld.global.nc.L2::evict_last.v8.b32 {%0,%1,%2,%3,%4,%5,%6,%7}, [%8];"
        : "=r"(a0),"=r"(a1),"=r"(a2),"=r"(a3),
          "=r"(a4),"=r"(a5),"=r"(a6),"=r"(a7) : "l"(p));
    F8 r;
    r.f[0]=__uint_as_float(a0); r.f[1]=__uint_as_float(a1);
    r.f[2]=__uint_as_float(a2); r.f[3]=__uint_as_float(a3);
    r.f[4]=__uint_as_float(a4); r.f[5]=__uint_as_float(a5);
    r.f[6]=__uint_as_float(a6); r.f[7]=__uint_as_float(a7);
    return r;
}

__device__ __forceinline__ void acc_one(float m, float s, float& bestM, float& maxU)
{
    if (m > 0.5f) bestM = fmaxf(bestM, s);
    else          maxU  = fmaxf(maxU,  s);
}

// w[0..7] = concat(a,b)[sh .. sh+8). sh uniform per row.
__device__ __forceinline__ void select8(const F8& a, const F8& b, int sh, float w[8])
{
    switch (sh) {
    case 0: w[0]=a.f[0];w[1]=a.f[1];w[2]=a.f[2];w[3]=a.f[3];w[4]=a.f[4];w[5]=a.f[5];w[6]=a.f[6];w[7]=a.f[7]; break;
    case 1: w[0]=a.f[1];w[1]=a.f[2];w[2]=a.f[3];w[3]=a.f[4];w[4]=a.f[5];w[5]=a.f[6];w[6]=a.f[7];w[7]=b.f[0]; break;
    case 2: w[0]=a.f[2];w[1]=a.f[3];w[2]=a.f[4];w[3]=a.f[5];w[4]=a.f[6];w[5]=a.f[7];w[6]=b.f[0];w[7]=b.f[1]; break;
    case 3: w[0]=a.f[3];w[1]=a.f[4];w[2]=a.f[5];w[3]=a.f[6];w[4]=a.f[7];w[5]=b.f[0];w[6]=b.f[1];w[7]=b.f[2]; break;
    case 4: w[0]=a.f[4];w[1]=a.f[5];w[2]=a.f[6];w[3]=a.f[7];w[4]=b.f[0];w[5]=b.f[1];w[6]=b.f[2];w[7]=b.f[3]; break;
    case 5: w[0]=a.f[5];w[1]=a.f[6];w[2]=a.f[7];w[3]=b.f[0];w[4]=b.f[1];w[5]=b.f[2];w[6]=b.f[3];w[7]=b.f[4]; break;
    case 6: w[0]=a.f[6];w[1]=a.f[7];w[2]=b.f[0];w[3]=b.f[1];w[4]=b.f[2];w[5]=b.f[3];w[6]=b.f[4];w[7]=b.f[5]; break;
    default:w[0]=a.f[7];w[1]=b.f[0];w[2]=b.f[1];w[3]=b.f[2];w[4]=b.f[3];w[5]=b.f[4];w[6]=b.f[5];w[7]=b.f[6]; break;
    }
}

__global__ __launch_bounds__(BLOCK, 12)
void mention_loss_kernel(const float* __restrict__ eps_scores,
                         const float* __restrict__ ana_scores,
                         const float* __restrict__ mask,
                         const float* __restrict__ link_costs,
                         const float* __restrict__ false_new_cost,
                         float* __restrict__ out)
{
    const int b    = (int)blockIdx.x;        // 0..2047
    const int tid  = (int)threadIdx.x;
    const int warp = tid >> 5;
    const int lane = tid & 31;

    __shared__ float sM[2][BLOCK / 32];
    __shared__ float sU[2][BLOCK / 32];

    const float lc0 = __ldg(link_costs + 0);    // false_link
    const float lc1 = __ldg(link_costs + 1);    // wrong_link
    const float fnc = __ldg(false_new_cost);

    #pragma unroll
    for (int r = 0; r < 2; ++r) {
        const int row = (r == 0) ? b : (NMENT - 1 - b);

        const float* __restrict__ mrow = mask + (size_t)row * NMENT;   // 32B-aligned
        const long long abase = ((long long)row * (row - 1)) >> 1;
        const int sh = (int)(abase & 7);
        const float* __restrict__ gA = ana_scores + (abase - sh);      // 32B-aligned

        float bestM = -CUDART_INF_F;
        float maxU  = -CUDART_INF_F;

        // Groups with j0 + 16 <= row: base block, next block, and the
        // corrective load are all fully in-bounds (abase + j0 + 16 <= TOTAL).
        const int nv = (row >= 16) ? ((row - 8) >> 3) : 0;

        for (int base = warp << 5; base < nv; base += BLOCK) {
            const int idx = min(base + lane, nv - 1);   // clamp: idempotent dup
            const int j0 = idx << 3;
            const F8 m = ldg_el8(mrow + j0);
            const F8 a = ldg_el8(gA + j0);
            F8 nb;
            if (sh != 0) {
                #pragma unroll
                for (int c = 0; c < 8; ++c)
                    nb.f[c] = __shfl_down_sync(0xffffffffu, a.f[c], 1);
                // Neighbor holds group min(base+lane+1, nv-1); that equals
                // idx+1 only if base+lane+1 < nv and lane < 31. Otherwise
                // load the true next block directly (in-bounds: j0+16<=row).
                if (lane == 31 || base + lane + 1 >= nv) {
                    nb = ldg_el8(gA + j0 + 8);
                }
            }
            float w[8];
            select8(a, nb, sh, w);
            #pragma unroll
            for (int c = 0; c < 8; ++c)
                acc_one(m.f[c], w[c], bestM, maxU);
        }
        // Scalar tail: j in [nv*8, row)  (< 16 elements per lane stride)
        for (int j = (nv << 3) + tid; j < row; j += BLOCK) {
            acc_one(__ldg(mrow + j), __ldg(ana_scores + abase + j), bestM, maxU);
        }

        // Warp reduction
        #pragma unroll
        for (int off = 16; off > 0; off >>= 1) {
            bestM = fmaxf(bestM, __shfl_xor_sync(0xffffffffu, bestM, off));
            maxU  = fmaxf(maxU,  __shfl_xor_sync(0xffffffffu, maxU,  off));
        }
        if (lane == 0) { sM[r][warp] = bestM; sU[r][warp] = maxU; }
    }

    __syncthreads();

    if (warp == 0 && lane < 2) {
        const int r   = lane;
        const int row = (r == 0) ? b : (NMENT - 1 - b);

        float bestM = fmaxf(fmaxf(sM[r][0], sM[r][1]), fmaxf(sM[r][2], sM[r][3]));
        float maxU  = fmaxf(fmaxf(sU[r][0], sU[r][1]), fmaxf(sU[r][2], sU[r][3]));

        const float nonana = __ldg(mask + (size_t)row * NMENT + row);   // diag
        const float e      = __ldg(eps_scores + row);
        if (nonana > 0.5f) bestM = fmaxf(bestM, e);

        const float row_cost = nonana * lc0 + (1.0f - nonana) * lc1;

        float loss = 0.0f;
        loss = fmaxf(loss, row_cost * (1.0f + maxU - bestM));   // -inf-safe
        const float dcost = (1.0f - nonana) * fnc;
        loss = fmaxf(loss, dcost * (1.0f + e - bestM));

        out[row] = loss;
    }
}

extern "C" void kernel_launch(void* const* d_in, const int* in_sizes, int n_in,
                              void* d_out, int out_size)
{
    const float* eps  = (const float*)d_in[0];
    const float* ana  = (const float*)d_in[1];
    const float* mask = (const float*)d_in[2];
    const float* lc   = (const float*)d_in[3];
    const float* fnc  = (const float*)d_in[4];
    float* out = (float*)d_out;

    mention_loss_kernel<<<NMENT / 2, BLOCK>>>(eps, ana, mask, lc, fnc, out);
}

// round 10
// speedup vs baseline: 1.0764x; 1.0764x over previous
#include <cuda_runtime.h>
#include <math_constants.h>

// N=4096 mention-ranking loss, one streaming pass.
// CTA b handles rows {b, 4095-b}. Phase 1 interleaves BOTH rows in one loop
// (4 independent load streams: mask0/ana0/mask1/ana1 -> doubled MLP per warp).
// Phase 2 streams the remainder of the long row with unroll 2.
// mask rows 16B-aligned -> float4; ana rows unaligned -> scalar LDG.

#define NMENT 4096
#define BLOCK 128

__device__ __forceinline__ void acc_one(float m, float s, float& bestM, float& maxU)
{
    if (m > 0.5f) bestM = fmaxf(bestM, s);
    else          maxU  = fmaxf(maxU,  s);
}

__device__ __forceinline__ void acc_g4(const float4 m, const float* a, int j,
                                       float& bestM, float& maxU)
{
    const float s0 = __ldg(a + j + 0);
    const float s1 = __ldg(a + j + 1);
    const float s2 = __ldg(a + j + 2);
    const float s3 = __ldg(a + j + 3);
    acc_one(m.x, s0, bestM, maxU);
    acc_one(m.y, s1, bestM, maxU);
    acc_one(m.z, s2, bestM, maxU);
    acc_one(m.w, s3, bestM, maxU);
}

__global__ __launch_bounds__(BLOCK, 12)
void mention_loss_kernel(const float* __restrict__ eps_scores,
                         const float* __restrict__ ana_scores,
                         const float* __restrict__ mask,
                         const float* __restrict__ link_costs,
                         const float* __restrict__ false_new_cost,
                         float* __restrict__ out)
{
    const int b    = (int)blockIdx.x;        // 0..2047
    const int tid  = (int)threadIdx.x;
    const int warp = tid >> 5;
    const int lane = tid & 31;

    const int r0 = b;                        // short row
    const int r1 = NMENT - 1 - b;            // long row

    const float* __restrict__ m0 = mask + (size_t)r0 * NMENT;
    const float* __restrict__ m1 = mask + (size_t)r1 * NMENT;
    const long long ab0 = ((long long)r0 * (r0 - 1)) >> 1;
    const long long ab1 = ((long long)r1 * (r1 - 1)) >> 1;
    const float* __restrict__ a0 = ana_scores + ab0;
    const float* __restrict__ a1 = ana_scores + ab1;
    const float4* __restrict__ m0v = (const float4*)m0;
    const float4* __restrict__ m1v = (const float4*)m1;

    float bM0 = -CUDART_INF_F, mU0 = -CUDART_INF_F;
    float bM1 = -CUDART_INF_F, mU1 = -CUDART_INF_F;

    const int nv0 = r0 >> 2;                 // full f4 groups of the short row
    const int nv1 = r1 >> 2;                 // full f4 groups of the long row

    // ---- Phase 1: both rows interleaved over groups [0, nv0) ----
    for (int v = tid; v < nv0; v += BLOCK) {
        const float4 q0 = __ldg(m0v + v);
        const float4 q1 = __ldg(m1v + v);
        const int j = v << 2;
        acc_g4(q0, a0, j, bM0, mU0);
        acc_g4(q1, a1, j, bM1, mU1);
    }
    // Short-row scalar tail: j in [nv0*4, r0)
    for (int j = (nv0 << 2) + tid; j < r0; j += BLOCK) {
        acc_one(__ldg(m0 + j), __ldg(a0 + j), bM0, mU0);
    }

    // ---- Phase 2: long-row remainder groups [nv0, nv1), unroll 2 ----
    int v = nv0 + tid;
    for (; v + BLOCK < nv1; v += 2 * BLOCK) {
        const float4 qa = __ldg(m1v + v);
        const float4 qb = __ldg(m1v + v + BLOCK);
        acc_g4(qa, a1, v << 2,            bM1, mU1);
        acc_g4(qb, a1, (v + BLOCK) << 2,  bM1, mU1);
    }
    for (; v < nv1; v += BLOCK) {
        const float4 qa = __ldg(m1v + v);
        acc_g4(qa, a1, v << 2, bM1, mU1);
    }
    // Long-row scalar tail: j in [nv1*4, r1)
    for (int j = (nv1 << 2) + tid; j < r1; j += BLOCK) {
        acc_one(__ldg(m1 + j), __ldg(a1 + j), bM1, mU1);
    }

    // ---- Reductions (both rows) ----
    __shared__ float sM[2][BLOCK / 32];
    __shared__ float sU[2][BLOCK / 32];

    #pragma unroll
    for (int off = 16; off > 0; off >>= 1) {
        bM0 = fmaxf(bM0, __shfl_xor_sync(0xffffffffu, bM0, off));
        mU0 = fmaxf(mU0, __shfl_xor_sync(0xffffffffu, mU0, off));
        bM1 = fmaxf(bM1, __shfl_xor_sync(0xffffffffu, bM1, off));
        mU1 = fmaxf(mU1, __shfl_xor_sync(0xffffffffu, mU1, off));
    }
    if (lane == 0) {
        sM[0][warp] = bM0; sU[0][warp] = mU0;
        sM[1][warp] = bM1; sU[1][warp] = mU1;
    }
    __syncthreads();

    if (warp == 0 && lane < 2) {
        const int r   = lane;
        const int row = (r == 0) ? r0 : r1;

        float bestM = fmaxf(fmaxf(sM[r][0], sM[r][1]), fmaxf(sM[r][2], sM[r][3]));
        float maxU  = fmaxf(fmaxf(sU[r][0], sU[r][1]), fmaxf(sU[r][2], sU[r][3]));

        const float nonana = __ldg(mask + (size_t)row * NMENT + row);   // diag
        const float e      = __ldg(eps_scores + row);
        if (nonana > 0.5f) bestM = fmaxf(bestM, e);

        const float lc0 = __ldg(link_costs + 0);    // false_link
        const float lc1 = __ldg(link_costs + 1);    // wrong_link
        const float fnc = __ldg(false_new_cost);

        const float row_cost = nonana * lc0 + (1.0f - nonana) * lc1;

        float loss = 0.0f;
        loss = fmaxf(loss, row_cost * (1.0f + maxU - bestM));   // -inf-safe
        const float dcost = (1.0f - nonana) * fnc;
        loss = fmaxf(loss, dcost * (1.0f + e - bestM));

        out[row] = loss;
    }
}

extern "C" void kernel_launch(void* const* d_in, const int* in_sizes, int n_in,
                              void* d_out, int out_size)
{
    const float* eps  = (const float*)d_in[0];
    const float* ana  = (const float*)d_in[1];
    const float* mask = (const float*)d_in[2];
    const float* lc   = (const float*)d_in[3];
    const float* fnc  = (const float*)d_in[4];
    float* out = (float*)d_out;

    mention_loss_kernel<<<NMENT / 2, BLOCK>>>(eps, ana, mask, lc, fnc, out);
}